// round 9
// baseline (speedup 1.0000x reference)
#include <cuda_runtime.h>
#include <cuda_fp16.h>

#define NB 2
#define NP 524288           // points per batch
#define NG 1024             // oversampled grid per dim
#define NF 512              // frequency grid per dim
#define BETA_F 4.712388980384690f   // 1.5*pi
#define DPI 3.14159265358979323846
// 2^40 grid scale (folded into d_cinv as 2^20 per dimension); exact inverse below
#define INV_SCALE (1.0f / 1099511627776.0f)

// packed-pair buffer geometry: [4 parity bufs][NB][colgroup 518][rowpair 520] uint4
// uint4 cell (cg, rp-index) of buffer (rp,cp) = half2 x4:
//   {rowA colA, rowA colB, rowB colA, rowB colB}
//   rowA = 2*rpi + rp, rowB = rowA+1, colA = 2*cg + cp, colB = colA+1
#define CGN 518
#define RPN 520
#define BUFSZ (CGN * RPN)   // per batch per parity buffer, in uint4

// ---------------- static device scratch (no allocations allowed) ----------------
__device__ float2 d_spec[NB * NG * NG];        // row-FFT result (only 512 rows/batch valid)
__device__ uint4  d_gP[4 * NB * BUFSZ];        // 4 parity-packed half2 grids (34.5 MB)
__device__ float  d_cinv[NF];                  // 2^20 / I0(M*arg) deconvolution coefficients
__device__ float2 d_tw[NG];                    // e^{-2 pi i j / 1024}

// ---------------- init: deconvolution coefficients + twiddles ----------------
__global__ void init_kernel() {
    int t = blockIdx.x * blockDim.x + threadIdx.x;
    if (t < NF) {
        double k   = (double)(t - 256);
        double w   = 2.0 * DPI * k / 1024.0;
        double bet = 1.5 * DPI;
        double arg = sqrt(bet * bet - w * w);
        double x   = 4.0 * arg;                 // M * arg, always >= 17.7
        double tt = 3.75 / x;
        double poly = 0.39894228 + tt*(0.01328592 + tt*(0.00225319 + tt*(-0.00157565 +
                      tt*(0.00916281 + tt*(-0.02057706 + tt*(0.02635537 +
                      tt*(-0.01647633 + tt*0.00392377)))))));
        double i0 = exp(x) / sqrt(x) * poly;
        d_cinv[t] = (float)(1048576.0 / i0);    // 2^20 per dim -> grid scaled by 2^40
    }
    if (t < NG) {
        double th = -2.0 * DPI * (double)t / 1024.0;
        d_tw[t] = make_float2((float)cos(th), (float)sin(th));
    }
}

__device__ __forceinline__ float2 cmulf(float2 a, float2 b) {
    return make_float2(a.x * b.x - a.y * b.y, a.x * b.y + a.y * b.x);
}

// ---------------- fused: deconvolve + ifftshift + 1024-pt row FFT ----------------
__global__ void fft_rows_fused(const float* __restrict__ fhat) {
    __shared__ float2 sA[1024];
    __shared__ float2 sB[1024];
    int bi = blockIdx.x;                  // [0, 1024): 2 batches x 512 nonzero rows
    int b  = bi >> 9;
    int rr = bi & 511;
    int m1 = (rr < 256) ? rr : rr + 512;        // output spectrum row
    int i1 = (rr < 256) ? rr + 256 : rr - 256;  // source fhat row
    float ci1 = d_cinv[i1];
    const float2* fh = (const float2*)fhat + (size_t)(b * 512 + i1) * 512;
    int t = threadIdx.x;                  // 512 threads
#pragma unroll
    for (int h = 0; h < 2; h++) {
        int m2 = t + h * 512;
        float2 v = make_float2(0.0f, 0.0f);
        if (m2 < 256 || m2 >= 768) {
            int i2 = (m2 < 256) ? m2 + 256 : m2 - 768;
            float2 f = fh[i2];
            float s = ci1 * d_cinv[i2];
            v = make_float2(f.x * s, f.y * s);
        }
        sA[m2] = v;
    }
    __syncthreads();
    float2* x = sA;
    float2* y = sB;
#pragma unroll
    for (int k = 0; k < 10; k++) {
        int s  = 1 << k;
        int sp = t & ~(s - 1);
        float2 a  = x[t];
        float2 c  = x[t + 512];
        float2 wp = d_tw[sp];
        float2 sum = make_float2(a.x + c.x, a.y + c.y);
        float2 dif = make_float2(a.x - c.x, a.y - c.y);
        y[t + sp]     = sum;
        y[t + sp + s] = cmulf(dif, wp);
        __syncthreads();
        float2* tmp = x; x = y; y = tmp;
    }
    float2* base = d_spec + (b << 20) + (m1 << 10);
    base[t]       = x[t];
    base[t + 512] = x[t + 512];
}

// ---------------- epilogue store helpers (with wrap duplication) ----------------
__device__ __forceinline__ void st_u4(uint4* base, int cg, int j, uint4 v) {
    base[cg * RPN + j] = v;
    if (cg < 3) base[(cg + 512) * RPN + j] = v;
    if (j < 3) {
        base[cg * RPN + j + 512] = v;
        if (cg < 3) base[(cg + 512) * RPN + j + 512] = v;
    }
}
__device__ __forceinline__ void st_h2(uint4* base, int cg, int j, int slot, __half2 v) {
    ((__half2*)(base + cg * RPN + j))[slot] = v;
    if (cg < 3) ((__half2*)(base + (cg + 512) * RPN + j))[slot] = v;
    if (j < 3) {
        ((__half2*)(base + cg * RPN + j + 512))[slot] = v;
        if (cg < 3) ((__half2*)(base + (cg + 512) * RPN + j + 512))[slot] = v;
    }
}
__device__ __forceinline__ uint4 pk4(__half2 a, __half2 b, __half2 c, __half2 d) {
    uint4 u;
    u.x = *reinterpret_cast<unsigned*>(&a);
    u.y = *reinterpret_cast<unsigned*>(&b);
    u.z = *reinterpret_cast<unsigned*>(&c);
    u.w = *reinterpret_cast<unsigned*>(&d);
    return u;
}

// ---------------- fused: 4-column 1024-pt FFT + packed-pair epilogue ----------------
__global__ void fft_cols_fused() {
    extern __shared__ float2 sm[];        // [0,4096) = buf A, [4096,8192) = buf B
    float2* x = sm;
    float2* y = sm + 4096;
    int bi = blockIdx.x;                  // [0, 512)
    int b  = bi >> 8;
    int c0 = (bi & 255) << 2;             // 4 columns per block
    int j  = threadIdx.x;                 // 512 threads
    int c  = j & 3;
    int tb = j >> 2;                      // [0, 128)

    const float2* spec = d_spec + (b << 20) + c0 + c;
#pragma unroll
    for (int q = 0; q < 4; q++) {
        int u = tb + (q << 7);            // butterfly index in [0, 512)
        float2 wp = d_tw[u];
        float2 v, s0, s1;
        if (u < 256) {
            v = spec[(size_t)u << 10];
            s0 = v;
            s1 = cmulf(v, wp);
        } else {
            v = spec[(size_t)(u + 512) << 10];
            s0 = v;
            s1 = cmulf(make_float2(-v.x, -v.y), wp);
        }
        x[((2 * u) << 2) + c]     = s0;
        x[((2 * u + 1) << 2) + c] = s1;
    }
    __syncthreads();

#pragma unroll
    for (int k = 1; k < 10; k++) {
        int s = 1 << k;
#pragma unroll
        for (int q = 0; q < 4; q++) {
            int u  = tb + (q << 7);
            int sp = u & ~(s - 1);
            float2 a  = x[(u << 2) + c];
            float2 cc = x[((u + 512) << 2) + c];
            float2 wp = d_tw[sp];
            float2 sum = make_float2(a.x + cc.x, a.y + cc.y);
            float2 dif = make_float2(a.x - cc.x, a.y - cc.y);
            y[((u + sp) << 2) + c]     = sum;
            y[((u + sp + s) << 2) + c] = cmulf(dif, wp);
        }
        __syncthreads();
        float2* tmp = x; x = y; y = tmp;
    }

    // ---- epilogue: packed row-pair / col-parity buffers (coalesced across j) ----
    // thread j = rowpair; needs rows 2j, 2j+1, 2j+2 (mod 1024) for rp=0 and rp=1
    {
        uint4* B00 = d_gP + (size_t)(0 * NB + b) * BUFSZ;
        uint4* B01 = d_gP + (size_t)(1 * NB + b) * BUFSZ;
        uint4* B10 = d_gP + (size_t)(2 * NB + b) * BUFSZ;
        uint4* B11 = d_gP + (size_t)(3 * NB + b) * BUFSZ;
        __half2 hv[3][4];
#pragma unroll
        for (int r = 0; r < 3; r++) {
            int row = (2 * j + r) & 1023;
#pragma unroll
            for (int cc = 0; cc < 4; cc++)
                hv[r][cc] = __float22half2_rn(x[(row << 2) + cc]);
        }
        int cgA = c0 >> 1;                // even colgroup (block-local full cells)
        int cgL = (cgA + 511) & 511;      // left partial colgroup (cp=1)
        // rp = 0: rows (2j, 2j+1) = hv[0], hv[1]
        st_u4(B00, cgA,     j, pk4(hv[0][0], hv[0][1], hv[1][0], hv[1][1]));
        st_u4(B00, cgA + 1, j, pk4(hv[0][2], hv[0][3], hv[1][2], hv[1][3]));
        st_u4(B01, cgA,     j, pk4(hv[0][1], hv[0][2], hv[1][1], hv[1][2]));
        st_h2(B01, cgL,     j, 1, hv[0][0]);
        st_h2(B01, cgL,     j, 3, hv[1][0]);
        st_h2(B01, cgA + 1, j, 0, hv[0][3]);
        st_h2(B01, cgA + 1, j, 2, hv[1][3]);
        // rp = 1: rows (2j+1, 2j+2) = hv[1], hv[2]
        st_u4(B10, cgA,     j, pk4(hv[1][0], hv[1][1], hv[2][0], hv[2][1]));
        st_u4(B10, cgA + 1, j, pk4(hv[1][2], hv[1][3], hv[2][2], hv[2][3]));
        st_u4(B11, cgA,     j, pk4(hv[1][1], hv[1][2], hv[2][1], hv[2][2]));
        st_h2(B11, cgL,     j, 1, hv[1][0]);
        st_h2(B11, cgL,     j, 3, hv[2][0]);
        st_h2(B11, cgA + 1, j, 0, hv[1][3]);
        st_h2(B11, cgA + 1, j, 2, hv[2][3]);
    }
}

// ---------------- Kaiser-Bessel time-domain window (one-sided exp approx) ----------------
__device__ __forceinline__ float kbwin_c(float s, float cst) {
    float u2 = fmaf(-s, s, 16.0f);            // M^2 - s^2
    if (u2 <= 0.0f) return 0.0f;
    float rinv = rsqrtf(u2);                  // 1/u
    float u    = u2 * rinv;
    return __expf(BETA_F * u) * rinv * cst;   // e^{bu}/(2 pi u) * extra scale
}

// ---------------- per-point 8x8 gather: 4 lanes x 4 packed uint4 chunks ----------------
__global__ void __launch_bounds__(256) gather_kernel(const float* __restrict__ xin,
                                                     float* __restrict__ out) {
    int tid  = blockIdx.x * blockDim.x + threadIdx.x;
    int cl   = tid & 3;                   // lane's colgroup offset within the patch
    int p    = tid >> 2;                  // point id, [0, NB*NP)
    int b    = p >> 19;
    float2 xy = ((const float2*)xin)[p];

    float xn1 = xy.x * 1024.0f;
    float fl1 = floorf(xn1);
    int   l01 = (int)fl1;
    float fr1 = xn1 - fl1;

    float xn2 = xy.y * 1024.0f;
    float fl2 = floorf(xn2);
    int   l02 = (int)fl2;
    float fr2 = xn2 - fl2;

    // lane cl owns taps 2cl and 2cl+1 of each dimension; w1 carries the 2^-40 unscale
    float o0  = (float)(2 * cl - 3);
    float w1a = kbwin_c(fr1 - o0,        0.159154943091895336f * INV_SCALE);
    float w1b = kbwin_c(fr1 - o0 - 1.0f, 0.159154943091895336f * INV_SCALE);
    float w2a = kbwin_c(fr2 - o0,        0.159154943091895336f);
    float w2b = kbwin_c(fr2 - o0 - 1.0f, 0.159154943091895336f);

    // broadcast the 8 row weights across the 4-lane group
    float w1[8];
#pragma unroll
    for (int d = 0; d < 4; d++) {
        w1[2 * d]     = __shfl_sync(0xffffffffu, w1a, d, 4);
        w1[2 * d + 1] = __shfl_sync(0xffffffffu, w1b, d, 4);
    }

    int r0 = (l01 - 3) & 1023;
    int c0 = (l02 - 3) & 1023;
    int rp  = r0 & 1, rp0 = r0 >> 1;
    int cp  = c0 & 1, cg0 = c0 >> 1;
    const uint4* gp = d_gP + (size_t)(((rp << 1) | cp) * NB + b) * BUFSZ
                    + (size_t)(cg0 + cl) * RPN + rp0;

    float accre = 0.0f, accim = 0.0f;
#pragma unroll
    for (int k = 0; k < 4; k++) {
        uint4 q = __ldg(gp + k);          // rows r0+2k, r0+2k+1; cols c0+2cl, +1
        float2 a0 = __half22float2(*reinterpret_cast<const __half2*>(&q.x));
        float2 a1 = __half22float2(*reinterpret_cast<const __half2*>(&q.y));
        float2 a2 = __half22float2(*reinterpret_cast<const __half2*>(&q.z));
        float2 a3 = __half22float2(*reinterpret_cast<const __half2*>(&q.w));
        float sreA = w2a * a0.x + w2b * a1.x;
        float simA = w2a * a0.y + w2b * a1.y;
        float sreB = w2a * a2.x + w2b * a3.x;
        float simB = w2a * a2.y + w2b * a3.y;
        accre = fmaf(w1[2 * k], sreA, fmaf(w1[2 * k + 1], sreB, accre));
        accim = fmaf(w1[2 * k], simA, fmaf(w1[2 * k + 1], simB, accim));
    }
    // reduce across the 4 cooperating lanes
    accre += __shfl_xor_sync(0xffffffffu, accre, 1);
    accim += __shfl_xor_sync(0xffffffffu, accim, 1);
    accre += __shfl_xor_sync(0xffffffffu, accre, 2);
    accim += __shfl_xor_sync(0xffffffffu, accim, 2);
    if (cl == 0)
        ((float2*)out)[p] = make_float2(accre, accim);
}

// ---------------- launch ----------------
extern "C" void kernel_launch(void* const* d_in, const int* in_sizes, int n_in,
                              void* d_out, int out_size) {
    const float* xin = (const float*)d_in[0];   // [B, P, 2]
    const float* fh  = (const float*)d_in[1];   // [B,512,512,2]
    if (n_in >= 2 && in_sizes[0] < in_sizes[1]) {
        const float* t = xin; xin = fh; fh = t;
    }
    cudaFuncSetAttribute(fft_cols_fused,
                         cudaFuncAttributeMaxDynamicSharedMemorySize, 65536);
    init_kernel<<<4, 256>>>();
    fft_rows_fused<<<NB * 512, 512>>>(fh);
    fft_cols_fused<<<NB * 256, 512, 65536>>>();
    gather_kernel<<<(NB * NP * 4) / 256, 256>>>(xin, (float*)d_out);
}

// round 12
// speedup vs baseline: 1.3143x; 1.3143x over previous
#include <cuda_runtime.h>
#include <cuda_fp16.h>

#define NB 2
#define NP 524288           // points per batch
#define NG 1024             // oversampled grid per dim
#define NF 512              // frequency grid per dim
#define BETA_F 4.712388980384690f   // 1.5*pi
#define DPI 3.14159265358979323846
// 2^40 grid scale (folded into d_cinv as 2^20 per dimension); exact inverse below
#define INV_SCALE (1.0f / 1099511627776.0f)

// packed-pair buffers: [4 parity (rp,cp)][NB][rowpair 516][colgroup 516] uint4
// cell (rpi, cg) of buffer (rp,cp) holds half2 x4:
//   {rA cA, rA cB, rB cA, rB cB},  rA=(2rpi+rp)&1023, rB=(2rpi+rp+1)&1023,
//                                  cA=(2cg+cp)&1023,  cB=(2cg+cp+1)&1023
#define CGN 516
#define RPN 516
#define BUFSZ (RPN * CGN)   // per batch per parity buffer, in uint4

// ---------------- static device scratch (no allocations allowed) ----------------
__device__ float2 d_spec[NB * NG * NG];        // FFT working grid (in-place rows->cols)
__device__ uint4  d_gP[4 * NB * BUFSZ];        // 4 parity-packed half2 grids (34 MB)
__device__ float  d_cinv[NF];                  // 2^20 / I0(M*arg) deconvolution coefficients
__device__ float2 d_tw[NG];                    // e^{-2 pi i j / 1024}

// ---------------- init: deconvolution coefficients + twiddles ----------------
__global__ void init_kernel() {
    int t = blockIdx.x * blockDim.x + threadIdx.x;
    if (t < NF) {
        double k   = (double)(t - 256);
        double w   = 2.0 * DPI * k / 1024.0;
        double bet = 1.5 * DPI;
        double arg = sqrt(bet * bet - w * w);
        double x   = 4.0 * arg;                 // M * arg, always >= 17.7
        double tt = 3.75 / x;
        double poly = 0.39894228 + tt*(0.01328592 + tt*(0.00225319 + tt*(-0.00157565 +
                      tt*(0.00916281 + tt*(-0.02057706 + tt*(0.02635537 +
                      tt*(-0.01647633 + tt*0.00392377)))))));
        double i0 = exp(x) / sqrt(x) * poly;
        d_cinv[t] = (float)(1048576.0 / i0);    // 2^20 per dim -> grid scaled by 2^40
    }
    if (t < NG) {
        double th = -2.0 * DPI * (double)t / 1024.0;
        d_tw[t] = make_float2((float)cos(th), (float)sin(th));
    }
}

__device__ __forceinline__ float2 cmulf(float2 a, float2 b) {
    return make_float2(a.x * b.x - a.y * b.y, a.x * b.y + a.y * b.x);
}

// ---------------- fused: deconvolve + ifftshift + 1024-pt row FFT ----------------
__global__ void fft_rows_fused(const float* __restrict__ fhat) {
    __shared__ float2 sA[1024];
    __shared__ float2 sB[1024];
    int bi = blockIdx.x;                  // [0, 1024): 2 batches x 512 nonzero rows
    int b  = bi >> 9;
    int rr = bi & 511;
    int m1 = (rr < 256) ? rr : rr + 512;        // output spectrum row
    int i1 = (rr < 256) ? rr + 256 : rr - 256;  // source fhat row
    float ci1 = d_cinv[i1];
    const float2* fh = (const float2*)fhat + (size_t)(b * 512 + i1) * 512;
    int t = threadIdx.x;                  // 512 threads
#pragma unroll
    for (int h = 0; h < 2; h++) {
        int m2 = t + h * 512;
        float2 v = make_float2(0.0f, 0.0f);
        if (m2 < 256 || m2 >= 768) {
            int i2 = (m2 < 256) ? m2 + 256 : m2 - 768;
            float2 f = fh[i2];
            float s = ci1 * d_cinv[i2];
            v = make_float2(f.x * s, f.y * s);
        }
        sA[m2] = v;
    }
    __syncthreads();
    float2* x = sA;
    float2* y = sB;
#pragma unroll
    for (int k = 0; k < 10; k++) {
        int s  = 1 << k;
        int sp = t & ~(s - 1);
        float2 a  = x[t];
        float2 c  = x[t + 512];
        float2 wp = d_tw[sp];
        float2 sum = make_float2(a.x + c.x, a.y + c.y);
        float2 dif = make_float2(a.x - c.x, a.y - c.y);
        y[t + sp]     = sum;
        y[t + sp + s] = cmulf(dif, wp);
        __syncthreads();
        float2* tmp = x; x = y; y = tmp;
    }
    float2* base = d_spec + (b << 20) + (m1 << 10);
    base[t]       = x[t];
    base[t + 512] = x[t + 512];
}

// ---------------- 4-column 1024-pt FFT, in-place in d_spec ----------------
__global__ void fft_cols_fused() {
    extern __shared__ float2 sm[];        // [0,4096) = buf A, [4096,8192) = buf B
    float2* x = sm;
    float2* y = sm + 4096;
    int bi = blockIdx.x;                  // [0, 512)
    int b  = bi >> 8;
    int c0 = (bi & 255) << 2;             // 4 columns per block
    int j  = threadIdx.x;                 // 512 threads
    int c  = j & 3;
    int tb = j >> 2;                      // [0, 128)

    const float2* spec = d_spec + (b << 20) + c0 + c;
    // stage 0: gmem -> shared, exploiting the zero middle band
#pragma unroll
    for (int q = 0; q < 4; q++) {
        int u = tb + (q << 7);            // butterfly index in [0, 512)
        float2 wp = d_tw[u];
        float2 v, s0, s1;
        if (u < 256) {
            v = spec[(size_t)u << 10];
            s0 = v;
            s1 = cmulf(v, wp);
        } else {
            v = spec[(size_t)(u + 512) << 10];
            s0 = v;
            s1 = cmulf(make_float2(-v.x, -v.y), wp);
        }
        x[((2 * u) << 2) + c]     = s0;
        x[((2 * u + 1) << 2) + c] = s1;
    }
    __syncthreads();

#pragma unroll
    for (int k = 1; k < 10; k++) {
        int s = 1 << k;
#pragma unroll
        for (int q = 0; q < 4; q++) {
            int u  = tb + (q << 7);
            int sp = u & ~(s - 1);
            float2 a  = x[(u << 2) + c];
            float2 cc = x[((u + 512) << 2) + c];
            float2 wp = d_tw[sp];
            float2 sum = make_float2(a.x + cc.x, a.y + cc.y);
            float2 dif = make_float2(a.x - cc.x, a.y - cc.y);
            y[((u + sp) << 2) + c]     = sum;
            y[((u + sp + s) << 2) + c] = cmulf(dif, wp);
        }
        __syncthreads();
        float2* tmp = x; x = y; y = tmp;
    }

    // write back in place (32B-contiguous per 4-lane group)
    float2* outp = d_spec + (b << 20) + c0 + c;
#pragma unroll
    for (int q = 0; q < 8; q++) {
        int r = tb + (q << 7);
        outp[(size_t)r << 10] = x[(r << 2) + c];
    }
}

// ---------------- pack: build the 4 parity buffers from d_spec ----------------
__global__ void pack_kernel() {
    int gid = blockIdx.x * blockDim.x + threadIdx.x;   // [0, NB*RPN*CGN)
    if (gid >= NB * RPN * CGN) return;
    int cg  = gid % CGN;
    int t   = gid / CGN;
    int rpi = t % RPN;
    int b   = t / RPN;

    const float2* g = d_spec + (b << 20);
    int r[3], cc[3];
#pragma unroll
    for (int i = 0; i < 3; i++) {
        r[i]  = (2 * rpi + i) & 1023;
        cc[i] = (2 * cg + i) & 1023;
    }
    __half2 h[3][3];
#pragma unroll
    for (int i = 0; i < 3; i++)
#pragma unroll
        for (int jj = 0; jj < 3; jj++)
            h[i][jj] = __float22half2_rn(__ldg(&g[((size_t)r[i] << 10) + cc[jj]]));

    size_t cell = (size_t)rpi * CGN + cg;
    uint4* P = d_gP + (size_t)b * BUFSZ + cell;
#pragma unroll
    for (int rp = 0; rp < 2; rp++)
#pragma unroll
        for (int cp = 0; cp < 2; cp++) {
            uint4 u;
            u.x = *reinterpret_cast<unsigned*>(&h[rp][cp]);
            u.y = *reinterpret_cast<unsigned*>(&h[rp][cp + 1]);
            u.z = *reinterpret_cast<unsigned*>(&h[rp + 1][cp]);
            u.w = *reinterpret_cast<unsigned*>(&h[rp + 1][cp + 1]);
            P[(size_t)((rp << 1) | cp) * NB * BUFSZ] = u;
        }
}

// ---------------- Kaiser-Bessel time-domain window (one-sided exp approx) ----------------
__device__ __forceinline__ float kbwin_c(float s, float cst) {
    float u2 = fmaf(-s, s, 16.0f);            // M^2 - s^2
    if (u2 <= 0.0f) return 0.0f;
    float rinv = rsqrtf(u2);                  // 1/u
    float u    = u2 * rinv;
    return __expf(BETA_F * u) * rinv * cst;   // e^{bu}/(2 pi u) * extra scale
}

// ---------------- per-point 8x8 gather: 4 lanes, cross-lane contiguous uint4 ----------------
__global__ void __launch_bounds__(256) gather_kernel(const float* __restrict__ xin,
                                                     float* __restrict__ out) {
    int tid  = blockIdx.x * blockDim.x + threadIdx.x;
    int cl   = tid & 3;                   // lane's colgroup offset within the patch
    int p    = tid >> 2;                  // point id, [0, NB*NP)
    int b    = p >> 19;
    float2 xy = ((const float2*)xin)[p];

    float xn1 = xy.x * 1024.0f;
    float fl1 = floorf(xn1);
    int   l01 = (int)fl1;
    float fr1 = xn1 - fl1;

    float xn2 = xy.y * 1024.0f;
    float fl2 = floorf(xn2);
    int   l02 = (int)fl2;
    float fr2 = xn2 - fl2;

    // lane cl owns taps 2cl and 2cl+1 of each dimension; w1 carries the 2^-40 unscale
    float o0  = (float)(2 * cl - 3);
    float w1a = kbwin_c(fr1 - o0,        0.159154943091895336f * INV_SCALE);
    float w1b = kbwin_c(fr1 - o0 - 1.0f, 0.159154943091895336f * INV_SCALE);
    float w2a = kbwin_c(fr2 - o0,        0.159154943091895336f);
    float w2b = kbwin_c(fr2 - o0 - 1.0f, 0.159154943091895336f);

    // broadcast the 8 row weights across the 4-lane group
    float w1[8];
#pragma unroll
    for (int d = 0; d < 4; d++) {
        w1[2 * d]     = __shfl_sync(0xffffffffu, w1a, d, 4);
        w1[2 * d + 1] = __shfl_sync(0xffffffffu, w1b, d, 4);
    }

    int r0 = (l01 - 3) & 1023;
    int c0 = (l02 - 3) & 1023;
    int rp  = r0 & 1, rp0 = r0 >> 1;
    int cp  = c0 & 1, cg0 = c0 >> 1;
    const uint4* gp = d_gP + (size_t)(((rp << 1) | cp) * NB + b) * BUFSZ
                    + (size_t)rp0 * CGN + cg0 + cl;

    float accre = 0.0f, accim = 0.0f;
#pragma unroll
    for (int k = 0; k < 4; k++) {
        uint4 q = __ldg(gp + k * CGN);    // rows r0+2k, r0+2k+1; cols c0+2cl, +1
        float2 a0 = __half22float2(*reinterpret_cast<const __half2*>(&q.x));
        float2 a1 = __half22float2(*reinterpret_cast<const __half2*>(&q.y));
        float2 a2 = __half22float2(*reinterpret_cast<const __half2*>(&q.z));
        float2 a3 = __half22float2(*reinterpret_cast<const __half2*>(&q.w));
        float sreA = w2a * a0.x + w2b * a1.x;
        float simA = w2a * a0.y + w2b * a1.y;
        float sreB = w2a * a2.x + w2b * a3.x;
        float simB = w2a * a2.y + w2b * a3.y;
        accre = fmaf(w1[2 * k], sreA, fmaf(w1[2 * k + 1], sreB, accre));
        accim = fmaf(w1[2 * k], simA, fmaf(w1[2 * k + 1], simB, accim));
    }
    // reduce across the 4 cooperating lanes
    accre += __shfl_xor_sync(0xffffffffu, accre, 1);
    accim += __shfl_xor_sync(0xffffffffu, accim, 1);
    accre += __shfl_xor_sync(0xffffffffu, accre, 2);
    accim += __shfl_xor_sync(0xffffffffu, accim, 2);
    if (cl == 0)
        ((float2*)out)[p] = make_float2(accre, accim);
}

// ---------------- launch ----------------
extern "C" void kernel_launch(void* const* d_in, const int* in_sizes, int n_in,
                              void* d_out, int out_size) {
    const float* xin = (const float*)d_in[0];   // [B, P, 2]
    const float* fh  = (const float*)d_in[1];   // [B,512,512,2]
    if (n_in >= 2 && in_sizes[0] < in_sizes[1]) {
        const float* t = xin; xin = fh; fh = t;
    }
    cudaFuncSetAttribute(fft_cols_fused,
                         cudaFuncAttributeMaxDynamicSharedMemorySize, 65536);
    init_kernel<<<4, 256>>>();
    fft_rows_fused<<<NB * 512, 512>>>(fh);
    fft_cols_fused<<<NB * 256, 512, 65536>>>();
    pack_kernel<<<(NB * RPN * CGN + 255) / 256, 256>>>();
    gather_kernel<<<(NB * NP * 4) / 256, 256>>>(xin, (float*)d_out);
}

// round 17
// speedup vs baseline: 1.4409x; 1.0963x over previous
#include <cuda_runtime.h>
#include <cuda_fp16.h>

#define NB 2
#define NP 524288           // points per batch
#define NG 1024             // oversampled grid per dim
#define NF 512              // frequency grid per dim
#define BETA_F 4.712388980384690f   // 1.5*pi
#define DPI 3.14159265358979323846
// 2^40 grid scale (folded into d_cinv as 2^20 per dimension); exact inverse below
#define INV_SCALE (1.0f / 1099511627776.0f)

// packed-pair buffers: [4 parity (rp,cp)][NB][rowpair 516][colgroup 516] uint4
// cell (rpi, cg) of buffer (rp,cp) holds half2 x4:
//   {rA cA, rA cB, rB cA, rB cB},  rA=(2rpi+rp)&1023, rB=(2rpi+rp+1)&1023,
//                                  cA=(2cg+cp)&1023,  cB=(2cg+cp+1)&1023
#define CGN 516
#define RPN 516
#define BUFSZ (RPN * CGN)   // per batch per parity buffer, in uint4

// ---------------- static device scratch (no allocations allowed) ----------------
__device__ float2 d_spec[NB * NG * NG];        // row-FFT result (float2)
__device__ unsigned d_gH[NB * NG * NG];        // col-FFT result as half2 (8.4 MB)
__device__ uint4  d_gP[4 * NB * BUFSZ];        // 4 parity-packed half2 grids (34 MB)
__device__ float  d_cinv[NF];                  // 2^20 / I0(M*arg) deconvolution coefficients
__device__ float2 d_tw[NG];                    // e^{-2 pi i j / 1024}

// ---------------- init: deconvolution coefficients + twiddles ----------------
__global__ void init_kernel() {
    int t = blockIdx.x * blockDim.x + threadIdx.x;
    if (t < NF) {
        double k   = (double)(t - 256);
        double w   = 2.0 * DPI * k / 1024.0;
        double bet = 1.5 * DPI;
        double arg = sqrt(bet * bet - w * w);
        double x   = 4.0 * arg;                 // M * arg, always >= 17.7
        double tt = 3.75 / x;
        double poly = 0.39894228 + tt*(0.01328592 + tt*(0.00225319 + tt*(-0.00157565 +
                      tt*(0.00916281 + tt*(-0.02057706 + tt*(0.02635537 +
                      tt*(-0.01647633 + tt*0.00392377)))))));
        double i0 = exp(x) / sqrt(x) * poly;
        d_cinv[t] = (float)(1048576.0 / i0);    // 2^20 per dim -> grid scaled by 2^40
    }
    if (t < NG) {
        double th = -2.0 * DPI * (double)t / 1024.0;
        d_tw[t] = make_float2((float)cos(th), (float)sin(th));
    }
}

__device__ __forceinline__ float2 cmulf(float2 a, float2 b) {
    return make_float2(a.x * b.x - a.y * b.y, a.x * b.y + a.y * b.x);
}
__device__ __forceinline__ float2 f2add(float2 a, float2 b) { return make_float2(a.x+b.x, a.y+b.y); }
__device__ __forceinline__ float2 f2sub(float2 a, float2 b) { return make_float2(a.x-b.x, a.y-b.y); }

// ---------------- fused: deconvolve + ifftshift + 1024-pt radix-4 row FFT ----------------
// 256 threads per row. Stage 0 (s=1) folds the zero middle band: x1 = x2 = 0.
__global__ void fft_rows_fused(const float* __restrict__ fhat) {
    __shared__ float2 sA[1024];
    __shared__ float2 sB[1024];
    int bi = blockIdx.x;                  // [0, 1024): 2 batches x 512 nonzero rows
    int b  = bi >> 9;
    int rr = bi & 511;
    int m1 = (rr < 256) ? rr : rr + 512;        // output spectrum row
    int i1 = (rr < 256) ? rr + 256 : rr - 256;  // source fhat row
    float ci1 = d_cinv[i1];
    const float2* fh = (const float2*)fhat + (size_t)(b * 512 + i1) * 512;
    int t = threadIdx.x;                  // 256 threads

    // nonzero quarters: m2=t -> i2=t+256 ; m2=t+768 -> i2=t
    float2 f0 = fh[t + 256];
    float2 f3 = fh[t];
    float s0c = ci1 * d_cinv[t + 256];
    float s3c = ci1 * d_cinv[t];
    float2 v0 = make_float2(f0.x * s0c, f0.y * s0c);
    float2 v3 = make_float2(f3.x * s3c, f3.y * s3c);

    // stage s=1: x0=v0, x1=0, x2=0, x3=v3 -> A=B=v0, C=v3, Dm=(-v3.y, v3.x)
    sA[4 * t]     = f2add(v0, v3);
    sA[4 * t + 1] = cmulf(make_float2(v0.x - v3.y, v0.y + v3.x), d_tw[t]);
    sA[4 * t + 2] = cmulf(f2sub(v0, v3), d_tw[2 * t]);
    sA[4 * t + 3] = cmulf(make_float2(v0.x + v3.y, v0.y - v3.x), d_tw[3 * t]);
    __syncthreads();

    float2* x = sA;
    float2* y = sB;
#pragma unroll
    for (int s = 4; s <= 256; s <<= 2) {
        int sq   = t & ~(s - 1);
        int base = 3 * sq + t;            // 4*sq + (t - sq)
        float2 x0 = x[t];
        float2 x1 = x[t + 256];
        float2 x2 = x[t + 512];
        float2 x3 = x[t + 768];
        float2 A = f2add(x0, x2), B = f2sub(x0, x2);
        float2 C = f2add(x1, x3), D = f2sub(x1, x3);
        float2 Dm = make_float2(D.y, -D.x);               // -i*D
        y[base]         = f2add(A, C);
        y[base + s]     = cmulf(f2add(B, Dm), d_tw[sq]);
        y[base + 2*s]   = cmulf(f2sub(A, C), d_tw[2 * sq]);
        y[base + 3*s]   = cmulf(f2sub(B, Dm), d_tw[3 * sq]);
        __syncthreads();
        float2* tmp = x; x = y; y = tmp;
    }
    float2* base = d_spec + (b << 20) + (m1 << 10);
#pragma unroll
    for (int h = 0; h < 4; h++)
        base[t + h * 256] = x[t + h * 256];
}

// ---------------- radix-4 4-column 1024-pt FFT -> half2 grid d_gH ----------------
__global__ void fft_cols_fused() {
    extern __shared__ float2 sm[];        // [0,4096) = buf A, [4096,8192) = buf B
    float2* x = sm;
    float2* y = sm + 4096;
    int bi = blockIdx.x;                  // [0, 512)
    int b  = bi >> 8;
    int c0 = (bi & 255) << 2;             // 4 columns per block
    int j  = threadIdx.x;                 // 512 threads
    int c  = j & 3;
    int tb = j >> 2;                      // [0, 128)

    const float2* spec = d_spec + (b << 20) + c0 + c;
    // stage s=1: rows u, u+768 nonzero; u+256, u+512 zero
#pragma unroll
    for (int q = 0; q < 2; q++) {
        int u = tb + (q << 7);            // [0, 256)
        float2 v0 = spec[(size_t)u << 10];
        float2 v3 = spec[(size_t)(u + 768) << 10];
        x[((4 * u) << 2) + c]     = f2add(v0, v3);
        x[((4 * u + 1) << 2) + c] = cmulf(make_float2(v0.x - v3.y, v0.y + v3.x), d_tw[u]);
        x[((4 * u + 2) << 2) + c] = cmulf(f2sub(v0, v3), d_tw[2 * u]);
        x[((4 * u + 3) << 2) + c] = cmulf(make_float2(v0.x + v3.y, v0.y - v3.x), d_tw[3 * u]);
    }
    __syncthreads();

#pragma unroll
    for (int s = 4; s <= 256; s <<= 2) {
#pragma unroll
        for (int q = 0; q < 2; q++) {
            int u    = tb + (q << 7);
            int sq   = u & ~(s - 1);
            int base = 3 * sq + u;
            float2 x0 = x[(u << 2) + c];
            float2 x1 = x[((u + 256) << 2) + c];
            float2 x2 = x[((u + 512) << 2) + c];
            float2 x3 = x[((u + 768) << 2) + c];
            float2 A = f2add(x0, x2), B = f2sub(x0, x2);
            float2 C = f2add(x1, x3), D = f2sub(x1, x3);
            float2 Dm = make_float2(D.y, -D.x);
            y[(base << 2) + c]             = f2add(A, C);
            y[((base + s) << 2) + c]       = cmulf(f2add(B, Dm), d_tw[sq]);
            y[((base + 2 * s) << 2) + c]   = cmulf(f2sub(A, C), d_tw[2 * sq]);
            y[((base + 3 * s) << 2) + c]   = cmulf(f2sub(B, Dm), d_tw[3 * sq]);
        }
        __syncthreads();
        float2* tmp = x; x = y; y = tmp;
    }

    // writeback as half2 (4-lane groups contiguous, 16B per group)
    unsigned* gh = d_gH + ((size_t)b << 20) + c0 + c;
#pragma unroll
    for (int q = 0; q < 8; q++) {
        int r = tb + (q << 7);
        __half2 h = __float22half2_rn(x[(r << 2) + c]);
        gh[(size_t)r << 10] = *reinterpret_cast<unsigned*>(&h);
    }
}

// ---------------- pack v2: smem-staged, coalesced parity-buffer build ----------------
// block = 4 rowpairs x all 516 colgroups; smem holds 9 rows x 1032 half2 (incl. wrap cols)
__global__ void __launch_bounds__(256) pack_kernel() {
    __shared__ uint4 sg[9][258];          // 9 rows x 1032 half2
    int blk = blockIdx.x;                 // [0, NB*129)
    int b   = blk / 129;
    int rb  = blk - b * 129;
    int rpi0 = rb * 4;
    int tid = threadIdx.x;

    const uint4* ghb = (const uint4*)(d_gH + ((size_t)b << 20));
    for (int i = tid; i < 9 * 256; i += 256) {
        int row = i >> 8;
        int cu  = i & 255;
        int ro  = (2 * rpi0 + row) & 1023;
        sg[row][cu] = ghb[((size_t)ro << 8) + cu];
    }
    if (tid < 18) {                       // wrap cols 1024..1031 = cols 0..7
        int row = tid >> 1, w = tid & 1;
        int ro  = (2 * rpi0 + row) & 1023;
        sg[row][256 + w] = ghb[((size_t)ro << 8) + w];
    }
    __syncthreads();

    const __half2* sh = (const __half2*)&sg[0][0];   // row stride 1032 half2
    for (int cg = tid; cg < 516; cg += 256) {
#pragma unroll
        for (int l = 0; l < 4; l++) {
            int rpi = rpi0 + l;           // <= 515
            // 3x3 half2 neighborhood for this (rowpair, colgroup)
            unsigned hv[3][3];
#pragma unroll
            for (int rr = 0; rr < 3; rr++)
#pragma unroll
                for (int cc = 0; cc < 3; cc++) {
                    __half2 v = sh[(2 * l + rr) * 1032 + 2 * cg + cc];
                    hv[rr][cc] = *reinterpret_cast<unsigned*>(&v);
                }
            size_t cell = (size_t)rpi * CGN + cg;
#pragma unroll
            for (int rp = 0; rp < 2; rp++)
#pragma unroll
                for (int cp = 0; cp < 2; cp++) {
                    uint4 u;
                    u.x = hv[rp][cp];
                    u.y = hv[rp][cp + 1];
                    u.z = hv[rp + 1][cp];
                    u.w = hv[rp + 1][cp + 1];
                    d_gP[(size_t)(((rp << 1) | cp) * NB + b) * BUFSZ + cell] = u;
                }
        }
    }
}

// ---------------- Kaiser-Bessel time-domain window (one-sided exp approx) ----------------
__device__ __forceinline__ float kbwin_c(float s, float cst) {
    float u2 = fmaf(-s, s, 16.0f);            // M^2 - s^2
    if (u2 <= 0.0f) return 0.0f;
    float rinv = rsqrtf(u2);                  // 1/u
    float u    = u2 * rinv;
    return __expf(BETA_F * u) * rinv * cst;   // e^{bu}/(2 pi u) * extra scale
}

// ---------------- per-point 8x8 gather: 4 lanes, cross-lane contiguous uint4 ----------------
__global__ void __launch_bounds__(256) gather_kernel(const float* __restrict__ xin,
                                                     float* __restrict__ out) {
    int tid  = blockIdx.x * blockDim.x + threadIdx.x;
    int cl   = tid & 3;                   // lane's colgroup offset within the patch
    int p    = tid >> 2;                  // point id, [0, NB*NP)
    int b    = p >> 19;
    float2 xy = ((const float2*)xin)[p];

    float xn1 = xy.x * 1024.0f;
    float fl1 = floorf(xn1);
    int   l01 = (int)fl1;
    float fr1 = xn1 - fl1;

    float xn2 = xy.y * 1024.0f;
    float fl2 = floorf(xn2);
    int   l02 = (int)fl2;
    float fr2 = xn2 - fl2;

    // lane cl owns taps 2cl and 2cl+1 of each dimension; w1 carries the 2^-40 unscale
    float o0  = (float)(2 * cl - 3);
    float w1a = kbwin_c(fr1 - o0,        0.159154943091895336f * INV_SCALE);
    float w1b = kbwin_c(fr1 - o0 - 1.0f, 0.159154943091895336f * INV_SCALE);
    float w2a = kbwin_c(fr2 - o0,        0.159154943091895336f);
    float w2b = kbwin_c(fr2 - o0 - 1.0f, 0.159154943091895336f);

    // broadcast the 8 row weights across the 4-lane group
    float w1[8];
#pragma unroll
    for (int d = 0; d < 4; d++) {
        w1[2 * d]     = __shfl_sync(0xffffffffu, w1a, d, 4);
        w1[2 * d + 1] = __shfl_sync(0xffffffffu, w1b, d, 4);
    }

    int r0 = (l01 - 3) & 1023;
    int c0 = (l02 - 3) & 1023;
    int rp  = r0 & 1, rp0 = r0 >> 1;
    int cp  = c0 & 1, cg0 = c0 >> 1;
    const uint4* gp = d_gP + (size_t)(((rp << 1) | cp) * NB + b) * BUFSZ
                    + (size_t)rp0 * CGN + cg0 + cl;

    float accre = 0.0f, accim = 0.0f;
#pragma unroll
    for (int k = 0; k < 4; k++) {
        uint4 q = __ldg(gp + k * CGN);    // rows r0+2k, r0+2k+1; cols c0+2cl, +1
        float2 a0 = __half22float2(*reinterpret_cast<const __half2*>(&q.x));
        float2 a1 = __half22float2(*reinterpret_cast<const __half2*>(&q.y));
        float2 a2 = __half22float2(*reinterpret_cast<const __half2*>(&q.z));
        float2 a3 = __half22float2(*reinterpret_cast<const __half2*>(&q.w));
        float sreA = w2a * a0.x + w2b * a1.x;
        float simA = w2a * a0.y + w2b * a1.y;
        float sreB = w2a * a2.x + w2b * a3.x;
        float simB = w2a * a2.y + w2b * a3.y;
        accre = fmaf(w1[2 * k], sreA, fmaf(w1[2 * k + 1], sreB, accre));
        accim = fmaf(w1[2 * k], simA, fmaf(w1[2 * k + 1], simB, accim));
    }
    // reduce across the 4 cooperating lanes
    accre += __shfl_xor_sync(0xffffffffu, accre, 1);
    accim += __shfl_xor_sync(0xffffffffu, accim, 1);
    accre += __shfl_xor_sync(0xffffffffu, accre, 2);
    accim += __shfl_xor_sync(0xffffffffu, accim, 2);
    if (cl == 0)
        ((float2*)out)[p] = make_float2(accre, accim);
}

// ---------------- launch ----------------
extern "C" void kernel_launch(void* const* d_in, const int* in_sizes, int n_in,
                              void* d_out, int out_size) {
    const float* xin = (const float*)d_in[0];   // [B, P, 2]
    const float* fh  = (const float*)d_in[1];   // [B,512,512,2]
    if (n_in >= 2 && in_sizes[0] < in_sizes[1]) {
        const float* t = xin; xin = fh; fh = t;
    }
    cudaFuncSetAttribute(fft_cols_fused,
                         cudaFuncAttributeMaxDynamicSharedMemorySize, 65536);
    init_kernel<<<4, 256>>>();
    fft_rows_fused<<<NB * 512, 256>>>(fh);
    fft_cols_fused<<<NB * 256, 512, 65536>>>();
    pack_kernel<<<NB * 129, 256>>>();
    gather_kernel<<<(NB * NP * 4) / 256, 256>>>(xin, (float*)d_out);
}